// round 1
// baseline (speedup 1.0000x reference)
#include <cuda_runtime.h>
#include <math.h>

// S4 diagonal complex SSM scan, chunked 3-pass formulation.
// L=4096 timesteps, D=1024 channels, N=16 complex states per channel.
// Pass 1: per (d, chunk) local scan from zero state -> chunk end states.
// Pass 2: per (d, n) cross-chunk scan with LamT = Lam^T -> chunk init states.
// Pass 3: per (d, chunk) scan with true init state (C folded in), emit output.

#define LL 4096
#define DD 1024
#define NN 16
#define NP 8        // f32x2 pairs of states
#define CC 64       // chunks
#define TT 64       // timesteps per chunk

// scratch: chunk end states (pass1) overwritten with chunk init states (pass2)
// layout: [(c*NN + n)*DD + d]
__device__ float g_S_re[CC * NN * DD];
__device__ float g_S_im[CC * NN * DD];

// ---------------- packed f32x2 helpers ----------------
struct f2 { unsigned long long v; };

__device__ __forceinline__ f2 f2pack(float lo, float hi) {
    f2 r; asm("mov.b64 %0, {%1, %2};" : "=l"(r.v) : "f"(lo), "f"(hi)); return r;
}
__device__ __forceinline__ void f2unpack(f2 a, float& lo, float& hi) {
    asm("mov.b64 {%0, %1}, %2;" : "=f"(lo), "=f"(hi) : "l"(a.v));
}
__device__ __forceinline__ f2 f2fma(f2 a, f2 b, f2 c) {
    f2 r; asm("fma.rn.f32x2 %0, %1, %2, %3;" : "=l"(r.v) : "l"(a.v), "l"(b.v), "l"(c.v)); return r;
}
__device__ __forceinline__ f2 f2mul(f2 a, f2 b) {
    f2 r; asm("mul.rn.f32x2 %0, %1, %2;" : "=l"(r.v) : "l"(a.v), "l"(b.v)); return r;
}
__device__ __forceinline__ f2 f2add(f2 a, f2 b) {
    f2 r; asm("add.rn.f32x2 %0, %1, %2;" : "=l"(r.v) : "l"(a.v), "l"(b.v)); return r;
}
__device__ __forceinline__ f2 f2zero() { f2 r; r.v = 0ull; return r; }

__device__ __forceinline__ float softplus_f(float v) {
    return (v > 20.0f) ? v : log1pf(expf(v));
}

// compute Lam = exp(dt * (A_re + i A_im)) for one (d,n)
__device__ __forceinline__ void lam_dn(float dt, float ar, float ai,
                                       float& lre, float& lim) {
    float m = expf(dt * ar);
    float s, c;
    sincosf(dt * ai, &s, &c);
    lre = m * c;
    lim = m * s;
}

// ---------------- pass 1: local chunk scans (end states only) ----------------
__global__ void __launch_bounds__(128)
s4_pass1(const float* __restrict__ x, const float* __restrict__ Delta,
         const float* __restrict__ A_re, const float* __restrict__ A_im,
         const float* __restrict__ B_re, const float* __restrict__ B_im) {
    const int d = blockIdx.x * blockDim.x + threadIdx.x;  // 0..DD-1
    const int c = blockIdx.y;                             // 0..CC-1

    const float dt = softplus_f(Delta[d]);

    f2 lre[NP], lim[NP], nlim[NP], wre[NP], wim[NP];
    #pragma unroll
    for (int j = 0; j < NP; j++) {
        float l0r, l0i, l1r, l1i;
        const int n0 = 2 * j, n1 = 2 * j + 1;
        lam_dn(dt, A_re[d * NN + n0], A_im[d * NN + n0], l0r, l0i);
        lam_dn(dt, A_re[d * NN + n1], A_im[d * NN + n1], l1r, l1i);
        lre[j]  = f2pack(l0r, l1r);
        lim[j]  = f2pack(l0i, l1i);
        nlim[j] = f2pack(-l0i, -l1i);
        wre[j]  = f2pack(dt * B_re[d * NN + n0], dt * B_re[d * NN + n1]);
        wim[j]  = f2pack(dt * B_im[d * NN + n0], dt * B_im[d * NN + n1]);
    }

    f2 hre[NP], him[NP];
    #pragma unroll
    for (int j = 0; j < NP; j++) { hre[j] = f2zero(); him[j] = f2zero(); }

    const float* xp = x + (size_t)c * TT * DD + d;
    #pragma unroll 1
    for (int tb = 0; tb < TT; tb += 4) {
        float xs[4];
        #pragma unroll
        for (int u = 0; u < 4; u++) xs[u] = xp[(tb + u) * DD];
        #pragma unroll
        for (int u = 0; u < 4; u++) {
            f2 x2 = f2pack(xs[u], xs[u]);
            #pragma unroll
            for (int j = 0; j < NP; j++) {
                f2 nr = f2fma(lre[j], hre[j], f2fma(nlim[j], him[j], f2mul(wre[j], x2)));
                f2 ni = f2fma(lre[j], him[j], f2fma(lim[j],  hre[j], f2mul(wim[j], x2)));
                hre[j] = nr; him[j] = ni;
            }
        }
    }

    #pragma unroll
    for (int j = 0; j < NP; j++) {
        float r0, r1, i0, i1;
        f2unpack(hre[j], r0, r1);
        f2unpack(him[j], i0, i1);
        g_S_re[(c * NN + 2 * j    ) * DD + d] = r0;
        g_S_re[(c * NN + 2 * j + 1) * DD + d] = r1;
        g_S_im[(c * NN + 2 * j    ) * DD + d] = i0;
        g_S_im[(c * NN + 2 * j + 1) * DD + d] = i1;
    }
}

// ---------------- pass 2: cross-chunk scan (ends -> inits, in place) --------
__global__ void __launch_bounds__(128)
s4_pass2(const float* __restrict__ Delta,
         const float* __restrict__ A_re, const float* __restrict__ A_im) {
    const int i = blockIdx.x * blockDim.x + threadIdx.x;  // 0..DD*NN-1
    const int d = i & (DD - 1);
    const int n = i >> 10;

    const float dt = softplus_f(Delta[d]);
    float lr, li;
    lam_dn(dt, A_re[d * NN + n], A_im[d * NN + n], lr, li);
    // LamT = Lam^64 via 6 complex squarings
    #pragma unroll
    for (int s = 0; s < 6; s++) {
        float nr = lr * lr - li * li;
        li = 2.0f * lr * li;
        lr = nr;
    }

    float hr = 0.0f, hi = 0.0f;  // state before chunk 0
    #pragma unroll 1
    for (int c = 0; c < CC; c++) {
        const int idx = (c * NN + n) * DD + d;
        const float er = g_S_re[idx];
        const float ei = g_S_im[idx];
        g_S_re[idx] = hr;   // init state of chunk c
        g_S_im[idx] = hi;
        const float tr = lr * hr - li * hi + er;
        hi = lr * hi + li * hr + ei;
        hr = tr;
    }
}

// ---------------- pass 3: full scan with init state, emit output ------------
__global__ void __launch_bounds__(128)
s4_pass3(const float* __restrict__ x, const float* __restrict__ Delta,
         const float* __restrict__ A_re, const float* __restrict__ A_im,
         const float* __restrict__ B_re, const float* __restrict__ B_im,
         const float* __restrict__ C_re, const float* __restrict__ C_im,
         const float* __restrict__ D_param, float* __restrict__ out) {
    const int d = blockIdx.x * blockDim.x + threadIdx.x;
    const int c = blockIdx.y;

    const float dt = softplus_f(Delta[d]);
    const float Dp = D_param[d];

    // g = C (.) h formulation: g' = Lam g + (C*dt*B) x, y = sum Re(g)
    f2 lre[NP], lim[NP], nlim[NP], wre[NP], wim[NP];  // w = C*dt*B (complex)
    f2 gre[NP], gim[NP];
    #pragma unroll
    for (int j = 0; j < NP; j++) {
        float vr[2], vi[2], gr[2], gi[2];
        #pragma unroll
        for (int k = 0; k < 2; k++) {
            const int n = 2 * j + k;
            float lr_, li_;
            lam_dn(dt, A_re[d * NN + n], A_im[d * NN + n], lr_, li_);
            if (k == 0) { lre[j] = f2pack(lr_, 0.f); }  // placeholder, fixed below
            const float cr = C_re[d * NN + n], ci = C_im[d * NN + n];
            const float br = dt * B_re[d * NN + n], bi = dt * B_im[d * NN + n];
            vr[k] = cr * br - ci * bi;
            vi[k] = cr * bi + ci * br;
            const float h0r = g_S_re[(c * NN + n) * DD + d];
            const float h0i = g_S_im[(c * NN + n) * DD + d];
            gr[k] = cr * h0r - ci * h0i;
            gi[k] = cr * h0i + ci * h0r;
            // stash lam parts in temp scalars via arrays
            if (k == 0) { vr[0] = vr[0]; }  // no-op
            // store lam packed after both k done
            if (k == 1) {
                float l0r, l0i, l1r, l1i;
                lam_dn(dt, A_re[d * NN + 2 * j], A_im[d * NN + 2 * j], l0r, l0i);
                l1r = lr_; l1i = li_;
                lre[j]  = f2pack(l0r, l1r);
                lim[j]  = f2pack(l0i, l1i);
                nlim[j] = f2pack(-l0i, -l1i);
            }
        }
        wre[j] = f2pack(vr[0], vr[1]);
        wim[j] = f2pack(vi[0], vi[1]);
        gre[j] = f2pack(gr[0], gr[1]);
        gim[j] = f2pack(gi[0], gi[1]);
    }

    const float* xp = x + (size_t)c * TT * DD + d;
    float* op = out + (size_t)c * TT * DD + d;

    #pragma unroll 1
    for (int tb = 0; tb < TT; tb += 4) {
        float xs[4];
        #pragma unroll
        for (int u = 0; u < 4; u++) xs[u] = xp[(tb + u) * DD];
        float ys[4];
        #pragma unroll
        for (int u = 0; u < 4; u++) {
            f2 x2 = f2pack(xs[u], xs[u]);
            #pragma unroll
            for (int j = 0; j < NP; j++) {
                f2 nr = f2fma(lre[j], gre[j], f2fma(nlim[j], gim[j], f2mul(wre[j], x2)));
                f2 ni = f2fma(lre[j], gim[j], f2fma(lim[j],  gre[j], f2mul(wim[j], x2)));
                gre[j] = nr; gim[j] = ni;
            }
            // y = sum of real parts (8 packed lanes -> tree reduce)
            f2 s01 = f2add(gre[0], gre[1]);
            f2 s23 = f2add(gre[2], gre[3]);
            f2 s45 = f2add(gre[4], gre[5]);
            f2 s67 = f2add(gre[6], gre[7]);
            f2 s03 = f2add(s01, s23);
            f2 s47 = f2add(s45, s67);
            f2 s   = f2add(s03, s47);
            float lo, hi;
            f2unpack(s, lo, hi);
            ys[u] = lo + hi + Dp * xs[u];
        }
        #pragma unroll
        for (int u = 0; u < 4; u++) op[(tb + u) * DD] = ys[u];
    }
}

extern "C" void kernel_launch(void* const* d_in, const int* in_sizes, int n_in,
                              void* d_out, int out_size) {
    const float* x     = (const float*)d_in[0];
    const float* Delta = (const float*)d_in[1];
    const float* A_re  = (const float*)d_in[2];
    const float* A_im  = (const float*)d_in[3];
    const float* B_re  = (const float*)d_in[4];
    const float* B_im  = (const float*)d_in[5];
    const float* C_re  = (const float*)d_in[6];
    const float* C_im  = (const float*)d_in[7];
    const float* Dp    = (const float*)d_in[8];
    float* out = (float*)d_out;

    dim3 blk(128);
    dim3 g13(DD / 128, CC);
    s4_pass1<<<g13, blk>>>(x, Delta, A_re, A_im, B_re, B_im);
    s4_pass2<<<(DD * NN) / 128, blk>>>(Delta, A_re, A_im);
    s4_pass3<<<g13, blk>>>(x, Delta, A_re, A_im, B_re, B_im, C_re, C_im, Dp, out);
}

// round 2
// speedup vs baseline: 1.8853x; 1.8853x over previous
#include <cuda_runtime.h>
#include <math.h>

// S4 diagonal complex SSM scan, chunked 3-pass formulation.
// L=4096 timesteps, D=1024 channels, N=16 complex states per channel.
// R2: states split across 2 threads (8 states each) -> half the registers,
//     2x threads; pass2 loads prefetched in batches of 8.
// Pass 1: per (d, half, chunk) local scan from zero -> chunk end states (8 states).
// Pass 2: per (d, n) cross-chunk scan with LamT = Lam^TT -> chunk init states.
// Pass 3: per (d, half, chunk) scan with true init state (C folded in);
//         the two half-threads combine via shfl.xor(1) and half 0 writes y.

#define LL 4096
#define DD 1024
#define NN 16
#define NP 4        // f32x2 pairs of states per thread (8 states)
#define CC 64       // chunks
#define TT 64       // timesteps per chunk

// scratch: chunk end states (pass1) overwritten with chunk init states (pass2)
// layout: [(c*NN + n)*DD + d]
__device__ float g_S_re[CC * NN * DD];
__device__ float g_S_im[CC * NN * DD];

// ---------------- packed f32x2 helpers ----------------
struct f2 { unsigned long long v; };

__device__ __forceinline__ f2 f2pack(float lo, float hi) {
    f2 r; asm("mov.b64 %0, {%1, %2};" : "=l"(r.v) : "f"(lo), "f"(hi)); return r;
}
__device__ __forceinline__ void f2unpack(f2 a, float& lo, float& hi) {
    asm("mov.b64 {%0, %1}, %2;" : "=f"(lo), "=f"(hi) : "l"(a.v));
}
__device__ __forceinline__ f2 f2fma(f2 a, f2 b, f2 c) {
    f2 r; asm("fma.rn.f32x2 %0, %1, %2, %3;" : "=l"(r.v) : "l"(a.v), "l"(b.v), "l"(c.v)); return r;
}
__device__ __forceinline__ f2 f2mul(f2 a, f2 b) {
    f2 r; asm("mul.rn.f32x2 %0, %1, %2;" : "=l"(r.v) : "l"(a.v), "l"(b.v)); return r;
}
__device__ __forceinline__ f2 f2add(f2 a, f2 b) {
    f2 r; asm("add.rn.f32x2 %0, %1, %2;" : "=l"(r.v) : "l"(a.v), "l"(b.v)); return r;
}
__device__ __forceinline__ f2 f2zero() { f2 r; r.v = 0ull; return r; }

__device__ __forceinline__ float softplus_f(float v) {
    return (v > 20.0f) ? v : log1pf(expf(v));
}

// Lam = exp(dt * (A_re + i A_im)) for one (d,n)
__device__ __forceinline__ void lam_dn(float dt, float ar, float ai,
                                       float& lre, float& lim) {
    float m = expf(dt * ar);
    float s, c;
    sincosf(dt * ai, &s, &c);
    lre = m * c;
    lim = m * s;
}

// ---------------- pass 1: local chunk scans (end states only) ----------------
__global__ void __launch_bounds__(128, 6)
s4_pass1(const float* __restrict__ x, const float* __restrict__ Delta,
         const float* __restrict__ A_re, const float* __restrict__ A_im,
         const float* __restrict__ B_re, const float* __restrict__ B_im) {
    const int gt   = blockIdx.x * blockDim.x + threadIdx.x;  // 0..2*DD-1
    const int d    = gt >> 1;
    const int half = gt & 1;
    const int nb   = half * (NN / 2);     // first state index for this thread
    const int c    = blockIdx.y;          // 0..CC-1

    const float dt = softplus_f(Delta[d]);

    f2 lre[NP], lim[NP], nlim[NP], wre[NP], wim[NP];
    #pragma unroll
    for (int j = 0; j < NP; j++) {
        const int n0 = nb + 2 * j, n1 = n0 + 1;
        float l0r, l0i, l1r, l1i;
        lam_dn(dt, A_re[d * NN + n0], A_im[d * NN + n0], l0r, l0i);
        lam_dn(dt, A_re[d * NN + n1], A_im[d * NN + n1], l1r, l1i);
        lre[j]  = f2pack(l0r, l1r);
        lim[j]  = f2pack(l0i, l1i);
        nlim[j] = f2pack(-l0i, -l1i);
        wre[j]  = f2pack(dt * B_re[d * NN + n0], dt * B_re[d * NN + n1]);
        wim[j]  = f2pack(dt * B_im[d * NN + n0], dt * B_im[d * NN + n1]);
    }

    f2 hre[NP], him[NP];
    #pragma unroll
    for (int j = 0; j < NP; j++) { hre[j] = f2zero(); him[j] = f2zero(); }

    const float* xp = x + (size_t)c * TT * DD + d;
    #pragma unroll 1
    for (int tb = 0; tb < TT; tb += 8) {
        float xs[8];
        #pragma unroll
        for (int u = 0; u < 8; u++) xs[u] = xp[(tb + u) * DD];
        #pragma unroll
        for (int u = 0; u < 8; u++) {
            f2 x2 = f2pack(xs[u], xs[u]);
            #pragma unroll
            for (int j = 0; j < NP; j++) {
                f2 nr = f2fma(lre[j], hre[j], f2fma(nlim[j], him[j], f2mul(wre[j], x2)));
                f2 ni = f2fma(lre[j], him[j], f2fma(lim[j],  hre[j], f2mul(wim[j], x2)));
                hre[j] = nr; him[j] = ni;
            }
        }
    }

    #pragma unroll
    for (int j = 0; j < NP; j++) {
        float r0, r1, i0, i1;
        f2unpack(hre[j], r0, r1);
        f2unpack(him[j], i0, i1);
        const int n0 = nb + 2 * j;
        g_S_re[(c * NN + n0    ) * DD + d] = r0;
        g_S_re[(c * NN + n0 + 1) * DD + d] = r1;
        g_S_im[(c * NN + n0    ) * DD + d] = i0;
        g_S_im[(c * NN + n0 + 1) * DD + d] = i1;
    }
}

// ---------------- pass 2: cross-chunk scan (ends -> inits, in place) --------
__global__ void __launch_bounds__(128)
s4_pass2(const float* __restrict__ Delta,
         const float* __restrict__ A_re, const float* __restrict__ A_im) {
    const int i = blockIdx.x * blockDim.x + threadIdx.x;  // 0..DD*NN-1
    const int d = i & (DD - 1);
    const int n = i >> 10;

    const float dt = softplus_f(Delta[d]);
    float lr, li;
    lam_dn(dt, A_re[d * NN + n], A_im[d * NN + n], lr, li);
    // LamT = Lam^64 via 6 complex squarings
    #pragma unroll
    for (int s = 0; s < 6; s++) {
        float nr = lr * lr - li * li;
        li = 2.0f * lr * li;
        lr = nr;
    }

    float hr = 0.0f, hi = 0.0f;  // state before chunk 0
    #pragma unroll 1
    for (int cb = 0; cb < CC; cb += 8) {
        // prefetch 8 chunk-end states (independent of the chain)
        float er[8], ei[8];
        #pragma unroll
        for (int u = 0; u < 8; u++) {
            const int idx = ((cb + u) * NN + n) * DD + d;
            er[u] = g_S_re[idx];
            ei[u] = g_S_im[idx];
        }
        #pragma unroll
        for (int u = 0; u < 8; u++) {
            const int idx = ((cb + u) * NN + n) * DD + d;
            g_S_re[idx] = hr;   // init state of chunk cb+u
            g_S_im[idx] = hi;
            const float tr = lr * hr - li * hi + er[u];
            hi = lr * hi + li * hr + ei[u];
            hr = tr;
        }
    }
}

// ---------------- pass 3: full scan with init state, emit output ------------
__global__ void __launch_bounds__(128, 6)
s4_pass3(const float* __restrict__ x, const float* __restrict__ Delta,
         const float* __restrict__ A_re, const float* __restrict__ A_im,
         const float* __restrict__ B_re, const float* __restrict__ B_im,
         const float* __restrict__ C_re, const float* __restrict__ C_im,
         const float* __restrict__ D_param, float* __restrict__ out) {
    const int gt   = blockIdx.x * blockDim.x + threadIdx.x;
    const int d    = gt >> 1;
    const int half = gt & 1;
    const int nb   = half * (NN / 2);
    const int c    = blockIdx.y;

    const float dt = softplus_f(Delta[d]);
    const float Dp = D_param[d];

    // g = C (.) h formulation: g' = Lam g + (C*dt*B) x, y = sum Re(g) over ALL n
    f2 lre[NP], lim[NP], nlim[NP], wre[NP], wim[NP];
    f2 gre[NP], gim[NP];
    #pragma unroll
    for (int j = 0; j < NP; j++) {
        const int n0 = nb + 2 * j, n1 = n0 + 1;
        float l0r, l0i, l1r, l1i;
        lam_dn(dt, A_re[d * NN + n0], A_im[d * NN + n0], l0r, l0i);
        lam_dn(dt, A_re[d * NN + n1], A_im[d * NN + n1], l1r, l1i);
        lre[j]  = f2pack(l0r, l1r);
        lim[j]  = f2pack(l0i, l1i);
        nlim[j] = f2pack(-l0i, -l1i);

        float vr[2], vi[2], gr[2], gi[2];
        #pragma unroll
        for (int k = 0; k < 2; k++) {
            const int n = n0 + k;
            const float cr = C_re[d * NN + n], ci = C_im[d * NN + n];
            const float br = dt * B_re[d * NN + n], bi = dt * B_im[d * NN + n];
            vr[k] = cr * br - ci * bi;
            vi[k] = cr * bi + ci * br;
            const float h0r = g_S_re[(c * NN + n) * DD + d];
            const float h0i = g_S_im[(c * NN + n) * DD + d];
            gr[k] = cr * h0r - ci * h0i;
            gi[k] = cr * h0i + ci * h0r;
        }
        wre[j] = f2pack(vr[0], vr[1]);
        wim[j] = f2pack(vi[0], vi[1]);
        gre[j] = f2pack(gr[0], gr[1]);
        gim[j] = f2pack(gi[0], gi[1]);
    }

    const float* xp = x + (size_t)c * TT * DD + d;
    float* op = out + (size_t)c * TT * DD + d;

    #pragma unroll 1
    for (int tb = 0; tb < TT; tb += 8) {
        float xs[8];
        #pragma unroll
        for (int u = 0; u < 8; u++) xs[u] = xp[(tb + u) * DD];
        float ys[8];
        #pragma unroll
        for (int u = 0; u < 8; u++) {
            f2 x2 = f2pack(xs[u], xs[u]);
            #pragma unroll
            for (int j = 0; j < NP; j++) {
                f2 nr = f2fma(lre[j], gre[j], f2fma(nlim[j], gim[j], f2mul(wre[j], x2)));
                f2 ni = f2fma(lre[j], gim[j], f2fma(lim[j],  gre[j], f2mul(wim[j], x2)));
                gre[j] = nr; gim[j] = ni;
            }
            // partial y = sum of this thread's 8 real parts
            f2 s01 = f2add(gre[0], gre[1]);
            f2 s23 = f2add(gre[2], gre[3]);
            f2 s   = f2add(s01, s23);
            float lo, hi;
            f2unpack(s, lo, hi);
            ys[u] = lo + hi;
        }
        #pragma unroll
        for (int u = 0; u < 8; u++) {
            // combine the two half-threads (adjacent lanes)
            float tot = ys[u] + __shfl_xor_sync(0xFFFFFFFFu, ys[u], 1);
            if (half == 0) op[(tb + u) * DD] = tot + Dp * xs[u];
        }
    }
}

extern "C" void kernel_launch(void* const* d_in, const int* in_sizes, int n_in,
                              void* d_out, int out_size) {
    const float* x     = (const float*)d_in[0];
    const float* Delta = (const float*)d_in[1];
    const float* A_re  = (const float*)d_in[2];
    const float* A_im  = (const float*)d_in[3];
    const float* B_re  = (const float*)d_in[4];
    const float* B_im  = (const float*)d_in[5];
    const float* C_re  = (const float*)d_in[6];
    const float* C_im  = (const float*)d_in[7];
    const float* Dp    = (const float*)d_in[8];
    float* out = (float*)d_out;

    dim3 blk(128);
    dim3 g13(2 * DD / 128, CC);
    s4_pass1<<<g13, blk>>>(x, Delta, A_re, A_im, B_re, B_im);
    s4_pass2<<<(DD * NN) / 128, blk>>>(Delta, A_re, A_im);
    s4_pass3<<<g13, blk>>>(x, Delta, A_re, A_im, B_re, B_im, C_re, C_im, Dp, out);
}

// round 3
// speedup vs baseline: 1.9642x; 1.0418x over previous
#include <cuda_runtime.h>
#include <math.h>

// S4 diagonal complex SSM scan, chunked 3-pass formulation.
// R3: states split 4-ways (4 states/thread, NP=2 f32x2 pairs) -> <=64 regs,
//     8 blocks/SM residency. Scratch relaid out as [c][d][n] so pass1/pass3
//     use float4 and pass2 is fully coalesced (idx = c*16384 + d*16 + n).
// Pass 1: per (d, quarter, chunk) local scan from zero -> chunk end states.
// Pass 2: per (d, n) cross-chunk scan with LamT = Lam^TT -> chunk init states.
// Pass 3: per (d, quarter, chunk) scan with init state (C folded in);
//         4 quarter-threads combine via shfl.xor(1),(2); quarter 0 writes y.

#define LL 4096
#define DD 1024
#define NN 16
#define NP 2        // f32x2 pairs of states per thread (4 states)
#define CC 64       // chunks
#define TT 64       // timesteps per chunk

// scratch: chunk end states (pass1) overwritten with chunk init states (pass2)
// layout: [(c*DD + d)*NN + n]
__device__ float g_S_re[CC * DD * NN];
__device__ float g_S_im[CC * DD * NN];

// ---------------- packed f32x2 helpers ----------------
struct f2 { unsigned long long v; };

__device__ __forceinline__ f2 f2pack(float lo, float hi) {
    f2 r; asm("mov.b64 %0, {%1, %2};" : "=l"(r.v) : "f"(lo), "f"(hi)); return r;
}
__device__ __forceinline__ void f2unpack(f2 a, float& lo, float& hi) {
    asm("mov.b64 {%0, %1}, %2;" : "=f"(lo), "=f"(hi) : "l"(a.v));
}
__device__ __forceinline__ f2 f2fma(f2 a, f2 b, f2 c) {
    f2 r; asm("fma.rn.f32x2 %0, %1, %2, %3;" : "=l"(r.v) : "l"(a.v), "l"(b.v), "l"(c.v)); return r;
}
__device__ __forceinline__ f2 f2mul(f2 a, f2 b) {
    f2 r; asm("mul.rn.f32x2 %0, %1, %2;" : "=l"(r.v) : "l"(a.v), "l"(b.v)); return r;
}
__device__ __forceinline__ f2 f2add(f2 a, f2 b) {
    f2 r; asm("add.rn.f32x2 %0, %1, %2;" : "=l"(r.v) : "l"(a.v), "l"(b.v)); return r;
}
__device__ __forceinline__ f2 f2zero() { f2 r; r.v = 0ull; return r; }

__device__ __forceinline__ float softplus_f(float v) {
    return (v > 20.0f) ? v : log1pf(expf(v));
}

__device__ __forceinline__ void lam_dn(float dt, float ar, float ai,
                                       float& lre, float& lim) {
    float m = expf(dt * ar);
    float s, c;
    sincosf(dt * ai, &s, &c);
    lre = m * c;
    lim = m * s;
}

// ---------------- pass 1: local chunk scans (end states only) ----------------
__global__ void __launch_bounds__(128, 8)
s4_pass1(const float* __restrict__ x, const float* __restrict__ Delta,
         const float* __restrict__ A_re, const float* __restrict__ A_im,
         const float* __restrict__ B_re, const float* __restrict__ B_im) {
    const int gt = blockIdx.x * blockDim.x + threadIdx.x;  // 0..4*DD-1
    const int d  = gt >> 2;
    const int q  = gt & 3;
    const int nb = q * 4;                 // first state index for this thread
    const int c  = blockIdx.y;            // 0..CC-1

    const float dt = softplus_f(Delta[d]);

    const float4 ar4 = *(const float4*)&A_re[d * NN + nb];
    const float4 ai4 = *(const float4*)&A_im[d * NN + nb];
    const float4 br4 = *(const float4*)&B_re[d * NN + nb];
    const float4 bi4 = *(const float4*)&B_im[d * NN + nb];

    float lr[4], li[4];
    lam_dn(dt, ar4.x, ai4.x, lr[0], li[0]);
    lam_dn(dt, ar4.y, ai4.y, lr[1], li[1]);
    lam_dn(dt, ar4.z, ai4.z, lr[2], li[2]);
    lam_dn(dt, ar4.w, ai4.w, lr[3], li[3]);

    f2 lre[NP], lim[NP], nlim[NP], wre[NP], wim[NP];
    lre[0]  = f2pack(lr[0], lr[1]);   lre[1]  = f2pack(lr[2], lr[3]);
    lim[0]  = f2pack(li[0], li[1]);   lim[1]  = f2pack(li[2], li[3]);
    nlim[0] = f2pack(-li[0], -li[1]); nlim[1] = f2pack(-li[2], -li[3]);
    wre[0]  = f2pack(dt * br4.x, dt * br4.y);
    wre[1]  = f2pack(dt * br4.z, dt * br4.w);
    wim[0]  = f2pack(dt * bi4.x, dt * bi4.y);
    wim[1]  = f2pack(dt * bi4.z, dt * bi4.w);

    f2 hre[NP], him[NP];
    #pragma unroll
    for (int j = 0; j < NP; j++) { hre[j] = f2zero(); him[j] = f2zero(); }

    const float* xp = x + (size_t)c * TT * DD + d;
    #pragma unroll 1
    for (int tb = 0; tb < TT; tb += 8) {
        float xs[8];
        #pragma unroll
        for (int u = 0; u < 8; u++) xs[u] = xp[(tb + u) * DD];
        #pragma unroll
        for (int u = 0; u < 8; u++) {
            f2 x2 = f2pack(xs[u], xs[u]);
            #pragma unroll
            for (int j = 0; j < NP; j++) {
                f2 nr = f2fma(lre[j], hre[j], f2fma(nlim[j], him[j], f2mul(wre[j], x2)));
                f2 ni = f2fma(lre[j], him[j], f2fma(lim[j],  hre[j], f2mul(wim[j], x2)));
                hre[j] = nr; him[j] = ni;
            }
        }
    }

    // store 4 end states as float4 (layout [c][d][n])
    float r0, r1, r2, r3, i0, i1, i2, i3;
    f2unpack(hre[0], r0, r1); f2unpack(hre[1], r2, r3);
    f2unpack(him[0], i0, i1); f2unpack(him[1], i2, i3);
    const int base = (c * DD + d) * NN + nb;
    *(float4*)&g_S_re[base] = make_float4(r0, r1, r2, r3);
    *(float4*)&g_S_im[base] = make_float4(i0, i1, i2, i3);
}

// ---------------- pass 2: cross-chunk scan (ends -> inits, in place) --------
__global__ void __launch_bounds__(128)
s4_pass2(const float* __restrict__ Delta,
         const float* __restrict__ A_re, const float* __restrict__ A_im) {
    const int i = blockIdx.x * blockDim.x + threadIdx.x;  // 0..DD*NN-1
    const int d = i >> 4;        // i = d*NN + n : coalesced everywhere

    const float dt = softplus_f(Delta[d]);
    float lr, li;
    lam_dn(dt, A_re[i], A_im[i], lr, li);
    // LamT = Lam^64 via 6 complex squarings
    #pragma unroll
    for (int s = 0; s < 6; s++) {
        float nr = lr * lr - li * li;
        li = 2.0f * lr * li;
        lr = nr;
    }

    float hr = 0.0f, hi = 0.0f;  // state before chunk 0
    #pragma unroll 1
    for (int cb = 0; cb < CC; cb += 8) {
        float er[8], ei[8];
        #pragma unroll
        for (int u = 0; u < 8; u++) {
            const int idx = (cb + u) * (DD * NN) + i;
            er[u] = g_S_re[idx];
            ei[u] = g_S_im[idx];
        }
        #pragma unroll
        for (int u = 0; u < 8; u++) {
            const int idx = (cb + u) * (DD * NN) + i;
            g_S_re[idx] = hr;   // init state of chunk cb+u
            g_S_im[idx] = hi;
            const float tr = lr * hr - li * hi + er[u];
            hi = lr * hi + li * hr + ei[u];
            hr = tr;
        }
    }
}

// ---------------- pass 3: full scan with init state, emit output ------------
__global__ void __launch_bounds__(128, 8)
s4_pass3(const float* __restrict__ x, const float* __restrict__ Delta,
         const float* __restrict__ A_re, const float* __restrict__ A_im,
         const float* __restrict__ B_re, const float* __restrict__ B_im,
         const float* __restrict__ C_re, const float* __restrict__ C_im,
         const float* __restrict__ D_param, float* __restrict__ out) {
    const int gt = blockIdx.x * blockDim.x + threadIdx.x;
    const int d  = gt >> 2;
    const int q  = gt & 3;
    const int nb = q * 4;
    const int c  = blockIdx.y;

    const float dt = softplus_f(Delta[d]);
    const float Dp = D_param[d];

    const float4 ar4 = *(const float4*)&A_re[d * NN + nb];
    const float4 ai4 = *(const float4*)&A_im[d * NN + nb];
    const float4 br4 = *(const float4*)&B_re[d * NN + nb];
    const float4 bi4 = *(const float4*)&B_im[d * NN + nb];
    const float4 cr4 = *(const float4*)&C_re[d * NN + nb];
    const float4 ci4 = *(const float4*)&C_im[d * NN + nb];
    const int base = (c * DD + d) * NN + nb;
    const float4 h0r4 = *(const float4*)&g_S_re[base];
    const float4 h0i4 = *(const float4*)&g_S_im[base];

    const float arr[4] = {ar4.x, ar4.y, ar4.z, ar4.w};
    const float aii[4] = {ai4.x, ai4.y, ai4.z, ai4.w};
    const float brr[4] = {br4.x, br4.y, br4.z, br4.w};
    const float bii[4] = {bi4.x, bi4.y, bi4.z, bi4.w};
    const float crr[4] = {cr4.x, cr4.y, cr4.z, cr4.w};
    const float cii[4] = {ci4.x, ci4.y, ci4.z, ci4.w};
    const float hrr[4] = {h0r4.x, h0r4.y, h0r4.z, h0r4.w};
    const float hii[4] = {h0i4.x, h0i4.y, h0i4.z, h0i4.w};

    // g = C (.) h formulation: g' = Lam g + (C*dt*B) x, y = sum Re(g) over ALL n
    float lr[4], li[4], vr[4], vi[4], gr[4], gi[4];
    #pragma unroll
    for (int k = 0; k < 4; k++) {
        lam_dn(dt, arr[k], aii[k], lr[k], li[k]);
        const float br = dt * brr[k], bi = dt * bii[k];
        vr[k] = crr[k] * br - cii[k] * bi;
        vi[k] = crr[k] * bi + cii[k] * br;
        gr[k] = crr[k] * hrr[k] - cii[k] * hii[k];
        gi[k] = crr[k] * hii[k] + cii[k] * hrr[k];
    }

    f2 lre[NP], lim[NP], nlim[NP], wre[NP], wim[NP], gre[NP], gim[NP];
    lre[0]  = f2pack(lr[0], lr[1]);   lre[1]  = f2pack(lr[2], lr[3]);
    lim[0]  = f2pack(li[0], li[1]);   lim[1]  = f2pack(li[2], li[3]);
    nlim[0] = f2pack(-li[0], -li[1]); nlim[1] = f2pack(-li[2], -li[3]);
    wre[0]  = f2pack(vr[0], vr[1]);   wre[1]  = f2pack(vr[2], vr[3]);
    wim[0]  = f2pack(vi[0], vi[1]);   wim[1]  = f2pack(vi[2], vi[3]);
    gre[0]  = f2pack(gr[0], gr[1]);   gre[1]  = f2pack(gr[2], gr[3]);
    gim[0]  = f2pack(gi[0], gi[1]);   gim[1]  = f2pack(gi[2], gi[3]);

    const float* xp = x + (size_t)c * TT * DD + d;
    float* op = out + (size_t)c * TT * DD + d;

    #pragma unroll 1
    for (int tb = 0; tb < TT; tb += 8) {
        float xs[8];
        #pragma unroll
        for (int u = 0; u < 8; u++) xs[u] = xp[(tb + u) * DD];
        #pragma unroll
        for (int u = 0; u < 8; u++) {
            f2 x2 = f2pack(xs[u], xs[u]);
            #pragma unroll
            for (int j = 0; j < NP; j++) {
                f2 nr = f2fma(lre[j], gre[j], f2fma(nlim[j], gim[j], f2mul(wre[j], x2)));
                f2 ni = f2fma(lre[j], gim[j], f2fma(lim[j],  gre[j], f2mul(wim[j], x2)));
                gre[j] = nr; gim[j] = ni;
            }
            // this thread's partial: sum of 4 real parts
            f2 s = f2add(gre[0], gre[1]);
            float lo, hi;
            f2unpack(s, lo, hi);
            float ys = lo + hi;
            // combine 4 quarter-threads (adjacent lanes)
            ys += __shfl_xor_sync(0xFFFFFFFFu, ys, 1);
            ys += __shfl_xor_sync(0xFFFFFFFFu, ys, 2);
            if (q == 0) op[(tb + u) * DD] = ys + Dp * xs[u];
        }
    }
}

extern "C" void kernel_launch(void* const* d_in, const int* in_sizes, int n_in,
                              void* d_out, int out_size) {
    const float* x     = (const float*)d_in[0];
    const float* Delta = (const float*)d_in[1];
    const float* A_re  = (const float*)d_in[2];
    const float* A_im  = (const float*)d_in[3];
    const float* B_re  = (const float*)d_in[4];
    const float* B_im  = (const float*)d_in[5];
    const float* C_re  = (const float*)d_in[6];
    const float* C_im  = (const float*)d_in[7];
    const float* Dp    = (const float*)d_in[8];
    float* out = (float*)d_out;

    dim3 blk(128);
    dim3 g13(4 * DD / 128, CC);
    s4_pass1<<<g13, blk>>>(x, Delta, A_re, A_im, B_re, B_im);
    s4_pass2<<<(DD * NN) / 128, blk>>>(Delta, A_re, A_im);
    s4_pass3<<<g13, blk>>>(x, Delta, A_re, A_im, B_re, B_im, C_re, C_im, Dp, out);
}

// round 4
// speedup vs baseline: 2.0359x; 1.0365x over previous
#include <cuda_runtime.h>
#include <math.h>

// S4 diagonal complex SSM scan, chunked 3-pass formulation.
// R4: double-buffered x prefetch in pass1/pass3 (hide ~600cyc load latency
//     behind compute), batched shfl epilogue in pass3, prefetched pass2.
// Layout of scratch: [(c*DD + d)*NN + n] -> float4 in pass1/3, coalesced pass2.

#define LL 4096
#define DD 1024
#define NN 16
#define NP 2        // f32x2 pairs of states per thread (4 states)
#define CC 64       // chunks
#define TT 64       // timesteps per chunk

__device__ float g_S_re[CC * DD * NN];
__device__ float g_S_im[CC * DD * NN];

// ---------------- packed f32x2 helpers ----------------
struct f2 { unsigned long long v; };

__device__ __forceinline__ f2 f2pack(float lo, float hi) {
    f2 r; asm("mov.b64 %0, {%1, %2};" : "=l"(r.v) : "f"(lo), "f"(hi)); return r;
}
__device__ __forceinline__ void f2unpack(f2 a, float& lo, float& hi) {
    asm("mov.b64 {%0, %1}, %2;" : "=f"(lo), "=f"(hi) : "l"(a.v));
}
__device__ __forceinline__ f2 f2fma(f2 a, f2 b, f2 c) {
    f2 r; asm("fma.rn.f32x2 %0, %1, %2, %3;" : "=l"(r.v) : "l"(a.v), "l"(b.v), "l"(c.v)); return r;
}
__device__ __forceinline__ f2 f2mul(f2 a, f2 b) {
    f2 r; asm("mul.rn.f32x2 %0, %1, %2;" : "=l"(r.v) : "l"(a.v), "l"(b.v)); return r;
}
__device__ __forceinline__ f2 f2add(f2 a, f2 b) {
    f2 r; asm("add.rn.f32x2 %0, %1, %2;" : "=l"(r.v) : "l"(a.v), "l"(b.v)); return r;
}
__device__ __forceinline__ f2 f2zero() { f2 r; r.v = 0ull; return r; }

__device__ __forceinline__ float softplus_f(float v) {
    return (v > 20.0f) ? v : log1pf(expf(v));
}

__device__ __forceinline__ void lam_dn(float dt, float ar, float ai,
                                       float& lre, float& lim) {
    float m = expf(dt * ar);
    float s, c;
    sincosf(dt * ai, &s, &c);
    lre = m * c;
    lim = m * s;
}

// ---------------- pass 1: local chunk scans (end states only) ----------------
__global__ void __launch_bounds__(128, 8)
s4_pass1(const float* __restrict__ x, const float* __restrict__ Delta,
         const float* __restrict__ A_re, const float* __restrict__ A_im,
         const float* __restrict__ B_re, const float* __restrict__ B_im) {
    const int gt = blockIdx.x * blockDim.x + threadIdx.x;  // 0..4*DD-1
    const int d  = gt >> 2;
    const int q  = gt & 3;
    const int nb = q * 4;
    const int c  = blockIdx.y;

    const float dt = softplus_f(Delta[d]);

    const float4 ar4 = *(const float4*)&A_re[d * NN + nb];
    const float4 ai4 = *(const float4*)&A_im[d * NN + nb];
    const float4 br4 = *(const float4*)&B_re[d * NN + nb];
    const float4 bi4 = *(const float4*)&B_im[d * NN + nb];

    float lr[4], li[4];
    lam_dn(dt, ar4.x, ai4.x, lr[0], li[0]);
    lam_dn(dt, ar4.y, ai4.y, lr[1], li[1]);
    lam_dn(dt, ar4.z, ai4.z, lr[2], li[2]);
    lam_dn(dt, ar4.w, ai4.w, lr[3], li[3]);

    f2 lre[NP], lim[NP], nlim[NP], wre[NP], wim[NP];
    lre[0]  = f2pack(lr[0], lr[1]);   lre[1]  = f2pack(lr[2], lr[3]);
    lim[0]  = f2pack(li[0], li[1]);   lim[1]  = f2pack(li[2], li[3]);
    nlim[0] = f2pack(-li[0], -li[1]); nlim[1] = f2pack(-li[2], -li[3]);
    wre[0]  = f2pack(dt * br4.x, dt * br4.y);
    wre[1]  = f2pack(dt * br4.z, dt * br4.w);
    wim[0]  = f2pack(dt * bi4.x, dt * bi4.y);
    wim[1]  = f2pack(dt * bi4.z, dt * bi4.w);

    f2 hre[NP], him[NP];
    #pragma unroll
    for (int j = 0; j < NP; j++) { hre[j] = f2zero(); him[j] = f2zero(); }

    const float* xp = x + (size_t)c * TT * DD + d;

    float xs[8];
    #pragma unroll
    for (int u = 0; u < 8; u++) xs[u] = xp[u * DD];

    #pragma unroll 1
    for (int tb = 0; tb < TT; tb += 8) {
        // prefetch next block before computing (hide load latency)
        const bool more = (tb + 8) < TT;
        const float* xnp = xp + (tb + 8) * DD;
        float xn[8];
        #pragma unroll
        for (int u = 0; u < 8; u++) xn[u] = more ? xnp[u * DD] : 0.0f;

        #pragma unroll
        for (int u = 0; u < 8; u++) {
            f2 x2 = f2pack(xs[u], xs[u]);
            #pragma unroll
            for (int j = 0; j < NP; j++) {
                f2 nr = f2fma(lre[j], hre[j], f2fma(nlim[j], him[j], f2mul(wre[j], x2)));
                f2 ni = f2fma(lre[j], him[j], f2fma(lim[j],  hre[j], f2mul(wim[j], x2)));
                hre[j] = nr; him[j] = ni;
            }
        }
        #pragma unroll
        for (int u = 0; u < 8; u++) xs[u] = xn[u];
    }

    float r0, r1, r2, r3, i0, i1, i2, i3;
    f2unpack(hre[0], r0, r1); f2unpack(hre[1], r2, r3);
    f2unpack(him[0], i0, i1); f2unpack(him[1], i2, i3);
    const int base = (c * DD + d) * NN + nb;
    *(float4*)&g_S_re[base] = make_float4(r0, r1, r2, r3);
    *(float4*)&g_S_im[base] = make_float4(i0, i1, i2, i3);
}

// ---------------- pass 2: cross-chunk scan (ends -> inits, in place) --------
__global__ void __launch_bounds__(128)
s4_pass2(const float* __restrict__ Delta,
         const float* __restrict__ A_re, const float* __restrict__ A_im) {
    const int i = blockIdx.x * blockDim.x + threadIdx.x;  // i = d*NN + n
    const int d = i >> 4;

    const float dt = softplus_f(Delta[d]);
    float lr, li;
    lam_dn(dt, A_re[i], A_im[i], lr, li);
    #pragma unroll
    for (int s = 0; s < 6; s++) {   // Lam^64
        float nr = lr * lr - li * li;
        li = 2.0f * lr * li;
        lr = nr;
    }

    float er[8], ei[8];
    #pragma unroll
    for (int u = 0; u < 8; u++) {
        const int idx = u * (DD * NN) + i;
        er[u] = g_S_re[idx];
        ei[u] = g_S_im[idx];
    }

    float hr = 0.0f, hi = 0.0f;
    #pragma unroll 1
    for (int cb = 0; cb < CC; cb += 8) {
        const bool more = (cb + 8) < CC;
        float er2[8], ei2[8];
        #pragma unroll
        for (int u = 0; u < 8; u++) {
            const int idx = (cb + 8 + u) * (DD * NN) + i;
            er2[u] = more ? g_S_re[idx] : 0.0f;
            ei2[u] = more ? g_S_im[idx] : 0.0f;
        }
        #pragma unroll
        for (int u = 0; u < 8; u++) {
            const int idx = (cb + u) * (DD * NN) + i;
            g_S_re[idx] = hr;
            g_S_im[idx] = hi;
            const float tr = lr * hr - li * hi + er[u];
            hi = lr * hi + li * hr + ei[u];
            hr = tr;
        }
        #pragma unroll
        for (int u = 0; u < 8; u++) { er[u] = er2[u]; ei[u] = ei2[u]; }
    }
}

// ---------------- pass 3: full scan with init state, emit output ------------
__global__ void __launch_bounds__(128, 6)
s4_pass3(const float* __restrict__ x, const float* __restrict__ Delta,
         const float* __restrict__ A_re, const float* __restrict__ A_im,
         const float* __restrict__ B_re, const float* __restrict__ B_im,
         const float* __restrict__ C_re, const float* __restrict__ C_im,
         const float* __restrict__ D_param, float* __restrict__ out) {
    const int gt = blockIdx.x * blockDim.x + threadIdx.x;
    const int d  = gt >> 2;
    const int q  = gt & 3;
    const int nb = q * 4;
    const int c  = blockIdx.y;

    const float dt = softplus_f(Delta[d]);
    const float Dp = D_param[d];

    const float4 ar4 = *(const float4*)&A_re[d * NN + nb];
    const float4 ai4 = *(const float4*)&A_im[d * NN + nb];
    const float4 br4 = *(const float4*)&B_re[d * NN + nb];
    const float4 bi4 = *(const float4*)&B_im[d * NN + nb];
    const float4 cr4 = *(const float4*)&C_re[d * NN + nb];
    const float4 ci4 = *(const float4*)&C_im[d * NN + nb];
    const int base = (c * DD + d) * NN + nb;
    const float4 h0r4 = *(const float4*)&g_S_re[base];
    const float4 h0i4 = *(const float4*)&g_S_im[base];

    const float arr[4] = {ar4.x, ar4.y, ar4.z, ar4.w};
    const float aii[4] = {ai4.x, ai4.y, ai4.z, ai4.w};
    const float brr[4] = {br4.x, br4.y, br4.z, br4.w};
    const float bii[4] = {bi4.x, bi4.y, bi4.z, bi4.w};
    const float crr[4] = {cr4.x, cr4.y, cr4.z, cr4.w};
    const float cii[4] = {ci4.x, ci4.y, ci4.z, ci4.w};
    const float hrr[4] = {h0r4.x, h0r4.y, h0r4.z, h0r4.w};
    const float hii[4] = {h0i4.x, h0i4.y, h0i4.z, h0i4.w};

    // g = C (.) h: g' = Lam g + (C*dt*B) x, y = sum Re(g) over all n
    float lr[4], li[4], vr[4], vi[4], gr[4], gi[4];
    #pragma unroll
    for (int k = 0; k < 4; k++) {
        lam_dn(dt, arr[k], aii[k], lr[k], li[k]);
        const float br = dt * brr[k], bi = dt * bii[k];
        vr[k] = crr[k] * br - cii[k] * bi;
        vi[k] = crr[k] * bi + cii[k] * br;
        gr[k] = crr[k] * hrr[k] - cii[k] * hii[k];
        gi[k] = crr[k] * hii[k] + cii[k] * hrr[k];
    }

    f2 lre[NP], lim[NP], nlim[NP], wre[NP], wim[NP], gre[NP], gim[NP];
    lre[0]  = f2pack(lr[0], lr[1]);   lre[1]  = f2pack(lr[2], lr[3]);
    lim[0]  = f2pack(li[0], li[1]);   lim[1]  = f2pack(li[2], li[3]);
    nlim[0] = f2pack(-li[0], -li[1]); nlim[1] = f2pack(-li[2], -li[3]);
    wre[0]  = f2pack(vr[0], vr[1]);   wre[1]  = f2pack(vr[2], vr[3]);
    wim[0]  = f2pack(vi[0], vi[1]);   wim[1]  = f2pack(vi[2], vi[3]);
    gre[0]  = f2pack(gr[0], gr[1]);   gre[1]  = f2pack(gr[2], gr[3]);
    gim[0]  = f2pack(gi[0], gi[1]);   gim[1]  = f2pack(gi[2], gi[3]);

    const float* xp = x + (size_t)c * TT * DD + d;
    float* op = out + (size_t)c * TT * DD + d;

    float xs[8];
    #pragma unroll
    for (int u = 0; u < 8; u++) xs[u] = xp[u * DD];

    #pragma unroll 1
    for (int tb = 0; tb < TT; tb += 8) {
        const bool more = (tb + 8) < TT;
        const float* xnp = xp + (tb + 8) * DD;
        float xn[8];
        #pragma unroll
        for (int u = 0; u < 8; u++) xn[u] = more ? xnp[u * DD] : 0.0f;

        float ys[8];
        #pragma unroll
        for (int u = 0; u < 8; u++) {
            f2 x2 = f2pack(xs[u], xs[u]);
            #pragma unroll
            for (int j = 0; j < NP; j++) {
                f2 nr = f2fma(lre[j], gre[j], f2fma(nlim[j], gim[j], f2mul(wre[j], x2)));
                f2 ni = f2fma(lre[j], gim[j], f2fma(lim[j],  gre[j], f2mul(wim[j], x2)));
                gre[j] = nr; gim[j] = ni;
            }
            f2 s = f2add(gre[0], gre[1]);
            float lo, hi;
            f2unpack(s, lo, hi);
            ys[u] = lo + hi;
        }
        // batched cross-thread reduce: 8 independent shfl chains pipeline
        #pragma unroll
        for (int u = 0; u < 8; u++)
            ys[u] += __shfl_xor_sync(0xFFFFFFFFu, ys[u], 1);
        #pragma unroll
        for (int u = 0; u < 8; u++)
            ys[u] += __shfl_xor_sync(0xFFFFFFFFu, ys[u], 2);
        if (q == 0) {
            #pragma unroll
            for (int u = 0; u < 8; u++)
                op[(tb + u) * DD] = ys[u] + Dp * xs[u];
        }
        #pragma unroll
        for (int u = 0; u < 8; u++) xs[u] = xn[u];
    }
}

extern "C" void kernel_launch(void* const* d_in, const int* in_sizes, int n_in,
                              void* d_out, int out_size) {
    const float* x     = (const float*)d_in[0];
    const float* Delta = (const float*)d_in[1];
    const float* A_re  = (const float*)d_in[2];
    const float* A_im  = (const float*)d_in[3];
    const float* B_re  = (const float*)d_in[4];
    const float* B_im  = (const float*)d_in[5];
    const float* C_re  = (const float*)d_in[6];
    const float* C_im  = (const float*)d_in[7];
    const float* Dp    = (const float*)d_in[8];
    float* out = (float*)d_out;

    dim3 blk(128);
    dim3 g13(4 * DD / 128, CC);
    s4_pass1<<<g13, blk>>>(x, Delta, A_re, A_im, B_re, B_im);
    s4_pass2<<<(DD * NN) / 128, blk>>>(Delta, A_re, A_im);
    s4_pass3<<<g13, blk>>>(x, Delta, A_re, A_im, B_re, B_im, C_re, C_im, Dp, out);
}

// round 5
// speedup vs baseline: 2.3604x; 1.1594x over previous
#include <cuda_runtime.h>
#include <math.h>

// S4 diagonal complex SSM scan, chunked 3-pass formulation.
// R5: x staged through shared memory (coalesced float4 tile load, broadcast
//     LDS reads) in pass1/pass3; pass1 uses k=4 step blocking
//     (h_{t+4} = Lam^4 h_t + Lam^3 w x1 + Lam^2 w x2 + Lam w x3 + w x4),
//     halving its FFMA2 count.

#define LL 4096
#define DD 1024
#define NN 16
#define NP 2        // f32x2 pairs of states per thread (4 states)
#define CC 64       // chunks
#define TT 64       // timesteps per chunk
#define DW 32       // d-channels per block (128 threads / 4 quarters)

__device__ float g_S_re[CC * DD * NN];
__device__ float g_S_im[CC * DD * NN];

// ---------------- packed f32x2 helpers ----------------
struct f2 { unsigned long long v; };

__device__ __forceinline__ f2 f2pack(float lo, float hi) {
    f2 r; asm("mov.b64 %0, {%1, %2};" : "=l"(r.v) : "f"(lo), "f"(hi)); return r;
}
__device__ __forceinline__ void f2unpack(f2 a, float& lo, float& hi) {
    asm("mov.b64 {%0, %1}, %2;" : "=f"(lo), "=f"(hi) : "l"(a.v));
}
__device__ __forceinline__ f2 f2fma(f2 a, f2 b, f2 c) {
    f2 r; asm("fma.rn.f32x2 %0, %1, %2, %3;" : "=l"(r.v) : "l"(a.v), "l"(b.v), "l"(c.v)); return r;
}
__device__ __forceinline__ f2 f2mul(f2 a, f2 b) {
    f2 r; asm("mul.rn.f32x2 %0, %1, %2;" : "=l"(r.v) : "l"(a.v), "l"(b.v)); return r;
}
__device__ __forceinline__ f2 f2add(f2 a, f2 b) {
    f2 r; asm("add.rn.f32x2 %0, %1, %2;" : "=l"(r.v) : "l"(a.v), "l"(b.v)); return r;
}
__device__ __forceinline__ f2 f2zero() { f2 r; r.v = 0ull; return r; }

__device__ __forceinline__ float softplus_f(float v) {
    return (v > 20.0f) ? v : log1pf(expf(v));
}

__device__ __forceinline__ void lam_dn(float dt, float ar, float ai,
                                       float& lre, float& lim) {
    float m = expf(dt * ar);
    float s, c;
    sincosf(dt * ai, &s, &c);
    lre = m * c;
    lim = m * s;
}

// cooperative coalesced load of this block's x tile: [TT][DW] floats
__device__ __forceinline__ void load_x_tile(float* xs_sm, const float* x,
                                            int c, int d0, int tid) {
    const float* xg = x + (size_t)c * TT * DD + d0;
    const int tt = tid >> 3;        // 0..15
    const int dq = (tid & 7) * 4;   // 0,4,..,28
    #pragma unroll
    for (int r = 0; r < 4; r++) {
        const int t = tt + r * 16;
        float4 v = *(const float4*)&xg[t * DD + dq];
        *(float4*)&xs_sm[t * DW + dq] = v;
    }
}

// ---------------- pass 1: local chunk scans, k=4 step blocking --------------
__global__ void __launch_bounds__(128, 6)
s4_pass1(const float* __restrict__ x, const float* __restrict__ Delta,
         const float* __restrict__ A_re, const float* __restrict__ A_im,
         const float* __restrict__ B_re, const float* __restrict__ B_im) {
    __shared__ float xs_sm[TT * DW];
    const int tid = threadIdx.x;
    const int dl  = tid >> 2;          // 0..31
    const int q   = tid & 3;
    const int d   = blockIdx.x * DW + dl;
    const int nb  = q * 4;
    const int c   = blockIdx.y;

    load_x_tile(xs_sm, x, c, blockIdx.x * DW, tid);

    // ---- parameter setup overlaps the tile load ----
    const float dt = softplus_f(Delta[d]);
    const float4 ar4 = *(const float4*)&A_re[d * NN + nb];
    const float4 ai4 = *(const float4*)&A_im[d * NN + nb];
    const float4 br4 = *(const float4*)&B_re[d * NN + nb];
    const float4 bi4 = *(const float4*)&B_im[d * NN + nb];
    const float arr[4] = {ar4.x, ar4.y, ar4.z, ar4.w};
    const float aii[4] = {ai4.x, ai4.y, ai4.z, ai4.w};
    const float brr[4] = {br4.x, br4.y, br4.z, br4.w};
    const float bii[4] = {bi4.x, bi4.y, bi4.z, bi4.w};

    float l4r[4], l4i[4];
    float c0r[4], c0i[4], c1r[4], c1i[4], c2r[4], c2i[4], c3r[4], c3i[4];
    #pragma unroll
    for (int k = 0; k < 4; k++) {
        float lr, li;
        lam_dn(dt, arr[k], aii[k], lr, li);
        c0r[k] = dt * brr[k];
        c0i[k] = dt * bii[k];
        c1r[k] = lr * c0r[k] - li * c0i[k];
        c1i[k] = lr * c0i[k] + li * c0r[k];
        c2r[k] = lr * c1r[k] - li * c1i[k];
        c2i[k] = lr * c1i[k] + li * c1r[k];
        c3r[k] = lr * c2r[k] - li * c2i[k];
        c3i[k] = lr * c2i[k] + li * c2r[k];
        const float l2r = lr * lr - li * li;
        const float l2i = 2.0f * lr * li;
        l4r[k] = l2r * l2r - l2i * l2i;
        l4i[k] = 2.0f * l2r * l2i;
    }

    f2 L4re[NP], L4im[NP], nL4im[NP];
    f2 C0r[NP], C0i[NP], C1r[NP], C1i[NP], C2r[NP], C2i[NP], C3r[NP], C3i[NP];
    #pragma unroll
    for (int j = 0; j < NP; j++) {
        const int a = 2 * j, b = 2 * j + 1;
        L4re[j]  = f2pack(l4r[a], l4r[b]);
        L4im[j]  = f2pack(l4i[a], l4i[b]);
        nL4im[j] = f2pack(-l4i[a], -l4i[b]);
        C0r[j] = f2pack(c0r[a], c0r[b]);  C0i[j] = f2pack(c0i[a], c0i[b]);
        C1r[j] = f2pack(c1r[a], c1r[b]);  C1i[j] = f2pack(c1i[a], c1i[b]);
        C2r[j] = f2pack(c2r[a], c2r[b]);  C2i[j] = f2pack(c2i[a], c2i[b]);
        C3r[j] = f2pack(c3r[a], c3r[b]);  C3i[j] = f2pack(c3i[a], c3i[b]);
    }

    f2 hre[NP], him[NP];
    #pragma unroll
    for (int j = 0; j < NP; j++) { hre[j] = f2zero(); him[j] = f2zero(); }

    __syncthreads();

    const float* xr = &xs_sm[dl];
    #pragma unroll 4
    for (int t = 0; t < TT; t += 4) {
        const float X1 = xr[(t + 0) * DW];
        const float X2 = xr[(t + 1) * DW];
        const float X3 = xr[(t + 2) * DW];
        const float X4 = xr[(t + 3) * DW];
        const f2 x1 = f2pack(X1, X1), x2 = f2pack(X2, X2);
        const f2 x3 = f2pack(X3, X3), x4 = f2pack(X4, X4);
        #pragma unroll
        for (int j = 0; j < NP; j++) {
            f2 tr = f2fma(C1r[j], x3, f2mul(C0r[j], x4));
            tr = f2fma(C2r[j], x2, tr);
            tr = f2fma(C3r[j], x1, tr);
            f2 ti = f2fma(C1i[j], x3, f2mul(C0i[j], x4));
            ti = f2fma(C2i[j], x2, ti);
            ti = f2fma(C3i[j], x1, ti);
            f2 nr = f2fma(L4re[j], hre[j], f2fma(nL4im[j], him[j], tr));
            f2 ni = f2fma(L4re[j], him[j], f2fma(L4im[j],  hre[j], ti));
            hre[j] = nr; him[j] = ni;
        }
    }

    float r0, r1, r2, r3, i0, i1, i2, i3;
    f2unpack(hre[0], r0, r1); f2unpack(hre[1], r2, r3);
    f2unpack(him[0], i0, i1); f2unpack(him[1], i2, i3);
    const int base = (c * DD + d) * NN + nb;
    *(float4*)&g_S_re[base] = make_float4(r0, r1, r2, r3);
    *(float4*)&g_S_im[base] = make_float4(i0, i1, i2, i3);
}

// ---------------- pass 2: cross-chunk scan (ends -> inits, in place) --------
__global__ void __launch_bounds__(128)
s4_pass2(const float* __restrict__ Delta,
         const float* __restrict__ A_re, const float* __restrict__ A_im) {
    const int i = blockIdx.x * blockDim.x + threadIdx.x;  // i = d*NN + n
    const int d = i >> 4;

    const float dt = softplus_f(Delta[d]);
    float lr, li;
    lam_dn(dt, A_re[i], A_im[i], lr, li);
    #pragma unroll
    for (int s = 0; s < 6; s++) {   // Lam^64
        float nr = lr * lr - li * li;
        li = 2.0f * lr * li;
        lr = nr;
    }

    float er[8], ei[8];
    #pragma unroll
    for (int u = 0; u < 8; u++) {
        const int idx = u * (DD * NN) + i;
        er[u] = g_S_re[idx];
        ei[u] = g_S_im[idx];
    }

    float hr = 0.0f, hi = 0.0f;
    #pragma unroll 1
    for (int cb = 0; cb < CC; cb += 8) {
        const bool more = (cb + 8) < CC;
        float er2[8], ei2[8];
        #pragma unroll
        for (int u = 0; u < 8; u++) {
            const int idx = (cb + 8 + u) * (DD * NN) + i;
            er2[u] = more ? g_S_re[idx] : 0.0f;
            ei2[u] = more ? g_S_im[idx] : 0.0f;
        }
        #pragma unroll
        for (int u = 0; u < 8; u++) {
            const int idx = (cb + u) * (DD * NN) + i;
            g_S_re[idx] = hr;
            g_S_im[idx] = hi;
            const float tr = lr * hr - li * hi + er[u];
            hi = lr * hi + li * hr + ei[u];
            hr = tr;
        }
        #pragma unroll
        for (int u = 0; u < 8; u++) { er[u] = er2[u]; ei[u] = ei2[u]; }
    }
}

// ---------------- pass 3: full scan with init state, emit output ------------
__global__ void __launch_bounds__(128, 8)
s4_pass3(const float* __restrict__ x, const float* __restrict__ Delta,
         const float* __restrict__ A_re, const float* __restrict__ A_im,
         const float* __restrict__ B_re, const float* __restrict__ B_im,
         const float* __restrict__ C_re, const float* __restrict__ C_im,
         const float* __restrict__ D_param, float* __restrict__ out) {
    __shared__ float xs_sm[TT * DW];
    const int tid = threadIdx.x;
    const int dl  = tid >> 2;
    const int q   = tid & 3;
    const int d   = blockIdx.x * DW + dl;
    const int nb  = q * 4;
    const int c   = blockIdx.y;

    load_x_tile(xs_sm, x, c, blockIdx.x * DW, tid);

    const float dt = softplus_f(Delta[d]);
    const float Dp = D_param[d];

    const float4 ar4 = *(const float4*)&A_re[d * NN + nb];
    const float4 ai4 = *(const float4*)&A_im[d * NN + nb];
    const float4 br4 = *(const float4*)&B_re[d * NN + nb];
    const float4 bi4 = *(const float4*)&B_im[d * NN + nb];
    const float4 cr4 = *(const float4*)&C_re[d * NN + nb];
    const float4 ci4 = *(const float4*)&C_im[d * NN + nb];
    const int base = (c * DD + d) * NN + nb;
    const float4 h0r4 = *(const float4*)&g_S_re[base];
    const float4 h0i4 = *(const float4*)&g_S_im[base];

    const float arr[4] = {ar4.x, ar4.y, ar4.z, ar4.w};
    const float aii[4] = {ai4.x, ai4.y, ai4.z, ai4.w};
    const float brr[4] = {br4.x, br4.y, br4.z, br4.w};
    const float bii[4] = {bi4.x, bi4.y, bi4.z, bi4.w};
    const float crr[4] = {cr4.x, cr4.y, cr4.z, cr4.w};
    const float cii[4] = {ci4.x, ci4.y, ci4.z, ci4.w};
    const float hrr[4] = {h0r4.x, h0r4.y, h0r4.z, h0r4.w};
    const float hii[4] = {h0i4.x, h0i4.y, h0i4.z, h0i4.w};

    // g = C (.) h: g' = Lam g + (C*dt*B) x, y = sum Re(g) over all n
    float lr[4], li[4], vr[4], vi[4], gr[4], gi[4];
    #pragma unroll
    for (int k = 0; k < 4; k++) {
        lam_dn(dt, arr[k], aii[k], lr[k], li[k]);
        const float br = dt * brr[k], bi = dt * bii[k];
        vr[k] = crr[k] * br - cii[k] * bi;
        vi[k] = crr[k] * bi + cii[k] * br;
        gr[k] = crr[k] * hrr[k] - cii[k] * hii[k];
        gi[k] = crr[k] * hii[k] + cii[k] * hrr[k];
    }

    f2 lre[NP], lim[NP], nlim[NP], wre[NP], wim[NP], gre[NP], gim[NP];
    lre[0]  = f2pack(lr[0], lr[1]);   lre[1]  = f2pack(lr[2], lr[3]);
    lim[0]  = f2pack(li[0], li[1]);   lim[1]  = f2pack(li[2], li[3]);
    nlim[0] = f2pack(-li[0], -li[1]); nlim[1] = f2pack(-li[2], -li[3]);
    wre[0]  = f2pack(vr[0], vr[1]);   wre[1]  = f2pack(vr[2], vr[3]);
    wim[0]  = f2pack(vi[0], vi[1]);   wim[1]  = f2pack(vi[2], vi[3]);
    gre[0]  = f2pack(gr[0], gr[1]);   gre[1]  = f2pack(gr[2], gr[3]);
    gim[0]  = f2pack(gi[0], gi[1]);   gim[1]  = f2pack(gi[2], gi[3]);

    __syncthreads();

    const float* xr = &xs_sm[dl];
    float* op = out + (size_t)c * TT * DD + d;

    #pragma unroll 1
    for (int tb = 0; tb < TT; tb += 8) {
        float xs[8], ys[8];
        #pragma unroll
        for (int u = 0; u < 8; u++) xs[u] = xr[(tb + u) * DW];
        #pragma unroll
        for (int u = 0; u < 8; u++) {
            f2 x2 = f2pack(xs[u], xs[u]);
            #pragma unroll
            for (int j = 0; j < NP; j++) {
                f2 nr = f2fma(lre[j], gre[j], f2fma(nlim[j], gim[j], f2mul(wre[j], x2)));
                f2 ni = f2fma(lre[j], gim[j], f2fma(lim[j],  gre[j], f2mul(wim[j], x2)));
                gre[j] = nr; gim[j] = ni;
            }
            f2 s = f2add(gre[0], gre[1]);
            float lo, hi;
            f2unpack(s, lo, hi);
            ys[u] = lo + hi;
        }
        #pragma unroll
        for (int u = 0; u < 8; u++)
            ys[u] += __shfl_xor_sync(0xFFFFFFFFu, ys[u], 1);
        #pragma unroll
        for (int u = 0; u < 8; u++)
            ys[u] += __shfl_xor_sync(0xFFFFFFFFu, ys[u], 2);
        if (q == 0) {
            #pragma unroll
            for (int u = 0; u < 8; u++)
                op[(tb + u) * DD] = ys[u] + Dp * xs[u];
        }
    }
}

extern "C" void kernel_launch(void* const* d_in, const int* in_sizes, int n_in,
                              void* d_out, int out_size) {
    const float* x     = (const float*)d_in[0];
    const float* Delta = (const float*)d_in[1];
    const float* A_re  = (const float*)d_in[2];
    const float* A_im  = (const float*)d_in[3];
    const float* B_re  = (const float*)d_in[4];
    const float* B_im  = (const float*)d_in[5];
    const float* C_re  = (const float*)d_in[6];
    const float* C_im  = (const float*)d_in[7];
    const float* Dp    = (const float*)d_in[8];
    float* out = (float*)d_out;

    dim3 blk(128);
    dim3 g13(DD / DW, CC);
    s4_pass1<<<g13, blk>>>(x, Delta, A_re, A_im, B_re, B_im);
    s4_pass2<<<(DD * NN) / 128, blk>>>(Delta, A_re, A_im);
    s4_pass3<<<g13, blk>>>(x, Delta, A_re, A_im, B_re, B_im, C_re, C_im, Dp, out);
}